// round 13
// baseline (speedup 1.0000x reference)
#include <cuda_runtime.h>
#include <cuda_bf16.h>
#include <math.h>
#include <stdint.h>

#define NODES  100000
#define NPAD   100096
#define DIM    512
#define BPAIRS 2048
#define ROWS   4096
#define GAMMA_ 3.0
#define LAMB_  20.0
#define TAU_   8.0
#define KS_    90.0f

#define BM 128
#define BN 128
#define BK 64
#define NCHUNK (DIM / BK)
#define STAGE_BYTES 32768
#define PR_STRIDE 516

// ---------------- scratch ----------------------------------------------------
__device__ __align__(256) __nv_bfloat16 g_Ab[(size_t)ROWS * DIM];
__device__ __align__(256) __nv_bfloat16 g_Al[(size_t)ROWS * DIM];
__device__ __align__(256) __nv_bfloat16 g_Eb[(size_t)NPAD * DIM];
__device__ __align__(256) __nv_bfloat16 g_ET[(size_t)DIM * NPAD];
__device__ __align__(256) float g_G [(size_t)DIM * DIM];
__device__ __align__(256) __nv_bfloat16 g_Gh[(size_t)DIM * DIM];
__device__ __align__(256) __nv_bfloat16 g_Gl[(size_t)DIM * DIM];
__device__ float  g_S[DIM], g_T[DIM];
__device__ double g_Q, g_Q2;
__device__ float g_asq[ROWS], g_pos[BPAIRS], g_esq[NODES];
__device__ float g_qrow[ROWS];
__device__ float g_sumexp[ROWS], g_cb[ROWS], g_rsig[ROWS], g_zb[ROWS];

// ---------------- PTX helpers --------------------------------------------------
__device__ __forceinline__ uint32_t cvta_smem(const void* p) {
    uint32_t a;
    asm("{ .reg .u64 t; cvta.to.shared.u64 t, %1; cvt.u32.u64 %0, t; }" : "=r"(a) : "l"(p));
    return a;
}
__device__ __forceinline__ void cpasync16(uint32_t s, const void* g) {
    asm volatile("cp.async.cg.shared.global [%0], [%1], 16;" :: "r"(s), "l"(g));
}
__device__ __forceinline__ uint32_t swz(uint32_t off) { return off ^ ((off >> 3) & 0x70); }
__device__ __forceinline__ void ldsm_x4(uint32_t* r, uint32_t addr) {
    asm volatile("ldmatrix.sync.aligned.m8n8.x4.shared.b16 {%0,%1,%2,%3}, [%4];"
                 : "=r"(r[0]), "=r"(r[1]), "=r"(r[2]), "=r"(r[3]) : "r"(addr));
}
__device__ __forceinline__ void mma16816(float* c, const uint32_t* a, const uint32_t* b) {
    asm volatile(
        "mma.sync.aligned.m16n8k16.row.col.f32.bf16.bf16.f32 "
        "{%0,%1,%2,%3}, {%4,%5,%6,%7}, {%8,%9}, {%0,%1,%2,%3};"
        : "+f"(c[0]), "+f"(c[1]), "+f"(c[2]), "+f"(c[3])
        : "r"(a[0]), "r"(a[1]), "r"(a[2]), "r"(a[3]), "r"(b[0]), "r"(b[1]));
}
#define WAIT1() asm volatile("cp.async.wait_group 1;" ::: "memory")
#define WAIT0() asm volatile("cp.async.wait_group 0;" ::: "memory")
#define COMMIT() asm volatile("cp.async.commit_group;" ::: "memory")

// ---------------- zero ----------------------------------------------------------
__global__ void k_zero() {
    int i = blockIdx.x * blockDim.x + threadIdx.x;
    if (i < DIM * DIM) g_G[i] = 0.f;
    if (i < ROWS) { g_sumexp[i] = 0.f; g_qrow[i] = 0.f; }
    if (i < DIM) { g_S[i] = 0.f; g_T[i] = 0.f; }
    if (i == 0) { g_Q = 0.0; g_Q2 = 0.0; }
}

// ---------------- fused prep (one pass over emb) --------------------------------
__global__ void __launch_bounds__(256) k_prep(const float* __restrict__ emb) {
    extern __shared__ float sm[];
    __shared__ float s_esq[32];
    const int tid = threadIdx.x;
    const int n0  = blockIdx.x * 32;
    const int w = tid >> 5, lane = tid & 31;

    #pragma unroll
    for (int i = 0; i < 16; i++) {
        int idx = tid + i * 256;
        int r = idx >> 7, c4 = idx & 127;
        float4 v = ((const float4*)emb)[(size_t)(n0 + r) * (DIM / 4) + c4];
        *(float4*)(sm + r * PR_STRIDE + c4 * 4) = v;
        __nv_bfloat162* q = (__nv_bfloat162*)(g_Eb + (size_t)(n0 + r) * DIM);
        q[c4 * 2 + 0] = __nv_bfloat162(__float2bfloat16_rn(v.x), __float2bfloat16_rn(v.y));
        q[c4 * 2 + 1] = __nv_bfloat162(__float2bfloat16_rn(v.z), __float2bfloat16_rn(v.w));
    }
    __syncthreads();

    #pragma unroll
    for (int q = 0; q < 4; q++) {
        int n = w * 4 + q;
        const float* row = sm + n * PR_STRIDE;
        float s = 0.f;
        #pragma unroll
        for (int i = 0; i < 4; i++) {
            float4 v = *(const float4*)(row + (lane + i * 32) * 4);
            s += v.x * v.x + v.y * v.y + v.z * v.z + v.w * v.w;
        }
        #pragma unroll
        for (int o = 16; o; o >>= 1) s += __shfl_xor_sync(0xffffffffu, s, o);
        if (lane == 0) { s_esq[n] = s; g_esq[n0 + n] = s; }
    }
    __syncthreads();

    #pragma unroll
    for (int dd = 0; dd < 2; dd++) {
        int d = tid + dd * 256;
        float sS = 0.f, sT = 0.f;
        #pragma unroll
        for (int n = 0; n < 32; n++) {
            float e = s_esq[n];
            float v = sm[n * PR_STRIDE + d];
            sS += v; sT += e * v;
        }
        atomicAdd(&g_S[d], sS);
        atomicAdd(&g_T[d], sT);
    }

    for (int d = w; d < DIM; d += 8)
        g_ET[(size_t)d * NPAD + n0 + lane] =
            __float2bfloat16_rn(sm[lane * PR_STRIDE + d]);

    if (tid < 32) {
        double e = (double)s_esq[tid], e2 = e * e;
        #pragma unroll
        for (int o = 16; o; o >>= 1) {
            e  += __shfl_xor_sync(0xffffffffu, e, o);
            e2 += __shfl_xor_sync(0xffffffffu, e2, o);
        }
        if (tid == 0) { atomicAdd(&g_Q, e); atomicAdd(&g_Q2, e2); }
    }
}

// gather A hi/lo + asq
__global__ void k_gather(const int* __restrict__ pairs, const float* __restrict__ emb) {
    int row = blockIdx.x * 8 + (threadIdx.x >> 5);
    if (row >= ROWS) return;
    int lane = threadIdx.x & 31;
    int p = row & (BPAIRS - 1), side = row >> 11;
    int node = pairs[2 * p + side];
    const float4* src = (const float4*)(emb + (size_t)node * DIM);
    float s = 0.f;
    #pragma unroll
    for (int i = lane; i < DIM / 4; i += 32) {
        float4 v = src[i];
        float f[4] = {v.x, v.y, v.z, v.w};
        __nv_bfloat16 h[4], l[4];
        #pragma unroll
        for (int q = 0; q < 4; q++) {
            h[q] = __float2bfloat16_rn(f[q]);
            l[q] = __float2bfloat16_rn(f[q] - __bfloat162float(h[q]));
            s += f[q] * f[q];
        }
        __nv_bfloat162* H = (__nv_bfloat162*)(g_Ab + (size_t)row * DIM + i * 4);
        __nv_bfloat162* L = (__nv_bfloat162*)(g_Al + (size_t)row * DIM + i * 4);
        H[0] = __nv_bfloat162(h[0], h[1]); H[1] = __nv_bfloat162(h[2], h[3]);
        L[0] = __nv_bfloat162(l[0], l[1]); L[1] = __nv_bfloat162(l[2], l[3]);
    }
    #pragma unroll
    for (int o = 16; o; o >>= 1) s += __shfl_xor_sync(0xffffffffu, s, o);
    if (lane == 0) g_asq[row] = s;
}

__global__ void k_pos(const int* __restrict__ pairs, const float* __restrict__ emb) {
    int p = blockIdx.x * 8 + (threadIdx.x >> 5);
    if (p >= BPAIRS) return;
    int lane = threadIdx.x & 31;
    int ln = pairs[2 * p], rn = pairs[2 * p + 1];
    const float4* a = (const float4*)(emb + (size_t)ln * DIM);
    const float4* b = (const float4*)(emb + (size_t)rn * DIM);
    float s = 0.f;
    #pragma unroll
    for (int i = lane; i < DIM / 4; i += 32) {
        float4 x = a[i], y = b[i];
        float dx = x.x - y.x, dy = x.y - y.y, dz = x.z - y.z, dw = x.w - y.w;
        s += dx * dx + dy * dy + dz * dz + dw * dw;
    }
    #pragma unroll
    for (int o = 16; o; o >>= 1) s += __shfl_xor_sync(0xffffffffu, s, o);
    if (lane == 0) g_pos[p] = s;
}

// ---------------- Gram G = E^T E (3-stage pipeline, symmetric-half) -------------
#define GZCH 68
__global__ void __launch_bounds__(256, 2) k_gram() {
    const int bx = blockIdx.x, by = blockIdx.y;
    if (by < bx) return;
    extern __shared__ __align__(1024) char dsm[];
    const int tid = threadIdx.x, lane = tid & 31, w = tid >> 5;
    const int m0 = bx * BM, n0 = by * BN;
    const uint32_t smb = cvta_smem(dsm);
    const int wm = (w >> 1) * 32, wn = (w & 1) * 64;
    const uint32_t aRow  = (uint32_t)(lane & 15);
    const uint32_t aColB = (uint32_t)((lane >> 4) * 16);
    const uint32_t grp   = (uint32_t)(lane >> 3);
    const uint32_t bRow  = (uint32_t)((lane & 7) + ((grp >> 1) * 8));
    const uint32_t bColB = (uint32_t)((grp & 1) * 16);

    float acc[2][8][4];
    #pragma unroll
    for (int mi = 0; mi < 2; mi++)
        #pragma unroll
        for (int ni = 0; ni < 8; ni++)
            #pragma unroll
            for (int q = 0; q < 4; q++) acc[mi][ni][q] = 0.f;

    const int cbase = blockIdx.z * GZCH;
    auto load_chunk = [&](int c, int st) {
        uint32_t sb = smb + (uint32_t)st * STAGE_BYTES;
        size_t node0 = (size_t)(cbase + c) * BK;
        #pragma unroll
        for (int i = 0; i < 4; i++) {
            int idx = tid + 256 * i, r = idx >> 3, seg = idx & 7;
            cpasync16(sb + swz((uint32_t)(r * 128 + seg * 16)),
                      g_ET + (size_t)(m0 + r) * NPAD + node0 + seg * 8);
        }
        #pragma unroll
        for (int i = 0; i < 4; i++) {
            int idx = tid + 256 * i, r = idx >> 3, seg = idx & 7;
            cpasync16(sb + 16384u + swz((uint32_t)(r * 128 + seg * 16)),
                      g_ET + (size_t)(n0 + r) * NPAD + node0 + seg * 8);
        }
        COMMIT();
    };

    load_chunk(0, 0);
    load_chunk(1, 1);
    int st_next = 2, st_cur = 0;
    for (int c = 0; c < GZCH; c++) {
        if (c < GZCH - 1) WAIT1(); else WAIT0();
        __syncthreads();
        if (c + 2 < GZCH) {
            load_chunk(c + 2, st_next);
            if (++st_next == 3) st_next = 0;
        }
        uint32_t sA = smb + (uint32_t)st_cur * STAGE_BYTES, sB = sA + 16384u;
        if (++st_cur == 3) st_cur = 0;
        #pragma unroll
        for (int kk = 0; kk < 4; kk++) {
            uint32_t a[2][4];
            #pragma unroll
            for (int mi = 0; mi < 2; mi++)
                ldsm_x4(a[mi], sA + swz((uint32_t)((wm + mi*16 + aRow)*128 + kk*32 + aColB)));
            uint32_t b[4][4];
            #pragma unroll
            for (int nt = 0; nt < 4; nt++)
                ldsm_x4(b[nt], sB + swz((uint32_t)((wn + nt*16 + bRow)*128 + kk*32 + bColB)));
            #pragma unroll
            for (int mi = 0; mi < 2; mi++)
                #pragma unroll
                for (int nt = 0; nt < 4; nt++) {
                    mma16816(acc[mi][nt*2+0], a[mi], &b[nt][0]);
                    mma16816(acc[mi][nt*2+1], a[mi], &b[nt][2]);
                }
        }
    }
    const int qr = lane >> 2, qc = lane & 3;
    #pragma unroll
    for (int mi = 0; mi < 2; mi++)
        #pragma unroll
        for (int h = 0; h < 2; h++) {
            int i = m0 + wm + mi * 16 + h * 8 + qr;
            #pragma unroll
            for (int ni = 0; ni < 8; ni++) {
                int j = n0 + wn + ni * 8 + qc * 2;
                float d0 = acc[mi][ni][h*2+0], d1 = acc[mi][ni][h*2+1];
                atomicAdd(&g_G[(size_t)i * DIM + j],     d0);
                atomicAdd(&g_G[(size_t)i * DIM + j + 1], d1);
                if (bx != by) {
                    atomicAdd(&g_G[(size_t)j * DIM + i],       d0);
                    atomicAdd(&g_G[(size_t)(j + 1) * DIM + i], d1);
                }
            }
        }
}

__global__ void k_gcvt() {
    int i = blockIdx.x * blockDim.x + threadIdx.x;
    if (i >= DIM * DIM) return;
    float g = g_G[i];
    __nv_bfloat16 h = __float2bfloat16_rn(g);
    g_Gh[i] = h;
    g_Gl[i] = __float2bfloat16_rn(g - __bfloat162float(h));
}

// ---------------- U = A*G, q = rowsum(U .* a) folded (3-stage) ------------------
__global__ void __launch_bounds__(256, 1) k_ug(const int* __restrict__ pairs,
                                               const float* __restrict__ emb) {
    extern __shared__ __align__(1024) char dsm[];
    const int tid = threadIdx.x, lane = tid & 31, w = tid >> 5;
    const int m0 = blockIdx.x * BM, n0 = blockIdx.y * BN;
    const uint32_t smb = cvta_smem(dsm);
    const uint32_t SS = 65536u;
    const int wm = (w >> 1) * 32, wn = (w & 1) * 64;
    const uint32_t aRow  = (uint32_t)(lane & 15);
    const uint32_t aColB = (uint32_t)((lane >> 4) * 16);
    const uint32_t grp   = (uint32_t)(lane >> 3);
    const uint32_t bRow  = (uint32_t)((lane & 7) + ((grp >> 1) * 8));
    const uint32_t bColB = (uint32_t)((grp & 1) * 16);

    float acc[2][8][4];
    #pragma unroll
    for (int mi = 0; mi < 2; mi++)
        #pragma unroll
        for (int ni = 0; ni < 8; ni++)
            #pragma unroll
            for (int q = 0; q < 4; q++) acc[mi][ni][q] = 0.f;

    auto load_chunk = [&](int c, int st) {
        uint32_t sb = smb + (uint32_t)st * SS;
        #pragma unroll
        for (int i = 0; i < 4; i++) {
            int idx = tid + 256 * i, r = idx >> 3, seg = idx & 7;
            uint32_t so = swz((uint32_t)(r * 128 + seg * 16));
            cpasync16(sb + so,          g_Ab + (size_t)(m0 + r) * DIM + c * BK + seg * 8);
            cpasync16(sb + 16384u + so, g_Al + (size_t)(m0 + r) * DIM + c * BK + seg * 8);
            cpasync16(sb + 32768u + so, g_Gh + (size_t)(n0 + r) * DIM + c * BK + seg * 8);
            cpasync16(sb + 49152u + so, g_Gl + (size_t)(n0 + r) * DIM + c * BK + seg * 8);
        }
        COMMIT();
    };

    load_chunk(0, 0);
    load_chunk(1, 1);
    int st_next = 2, st_cur = 0;
    for (int c = 0; c < NCHUNK; c++) {
        if (c < NCHUNK - 1) WAIT1(); else WAIT0();
        __syncthreads();
        if (c + 2 < NCHUNK) {
            load_chunk(c + 2, st_next);
            if (++st_next == 3) st_next = 0;
        }
        uint32_t sb = smb + (uint32_t)st_cur * SS;
        if (++st_cur == 3) st_cur = 0;
        #pragma unroll
        for (int kk = 0; kk < 4; kk++) {
            uint32_t ah[2][4], al[2][4];
            #pragma unroll
            for (int mi = 0; mi < 2; mi++) {
                uint32_t so = swz((uint32_t)((wm + mi*16 + aRow)*128 + kk*32 + aColB));
                ldsm_x4(ah[mi], sb + so);
                ldsm_x4(al[mi], sb + 16384u + so);
            }
            uint32_t gh[4][4], gl[4][4];
            #pragma unroll
            for (int nt = 0; nt < 4; nt++) {
                uint32_t so = swz((uint32_t)((wn + nt*16 + bRow)*128 + kk*32 + bColB));
                ldsm_x4(gh[nt], sb + 32768u + so);
                ldsm_x4(gl[nt], sb + 49152u + so);
            }
            #pragma unroll
            for (int mi = 0; mi < 2; mi++)
                #pragma unroll
                for (int nt = 0; nt < 4; nt++) {
                    mma16816(acc[mi][nt*2+0], ah[mi], &gh[nt][0]);
                    mma16816(acc[mi][nt*2+1], ah[mi], &gh[nt][2]);
                    mma16816(acc[mi][nt*2+0], ah[mi], &gl[nt][0]);
                    mma16816(acc[mi][nt*2+1], ah[mi], &gl[nt][2]);
                    mma16816(acc[mi][nt*2+0], al[mi], &gh[nt][0]);
                    mma16816(acc[mi][nt*2+1], al[mi], &gh[nt][2]);
                }
        }
    }

    const int qr = lane >> 2, qc = lane & 3;
    #pragma unroll
    for (int mi = 0; mi < 2; mi++)
        #pragma unroll
        for (int h = 0; h < 2; h++) {
            int row = m0 + wm + mi * 16 + h * 8 + qr;
            int p = row & (BPAIRS - 1), side = row >> 11;
            int node = pairs[2 * p + side];
            const float* arow = emb + (size_t)node * DIM + n0;
            float qs = 0.f;
            #pragma unroll
            for (int ni = 0; ni < 8; ni++) {
                int col = wn + ni * 8 + qc * 2;
                qs += acc[mi][ni][h*2+0] * arow[col]
                    + acc[mi][ni][h*2+1] * arow[col + 1];
            }
            #pragma unroll
            for (int o = 1; o < 4; o <<= 1)
                qs += __shfl_xor_sync(0xffffffffu, qs, o);
            if (qc == 0) atomicAdd(&g_qrow[row], qs);
        }
}

// ---------------- per-row analytic stats ----------------------------------------
__global__ void __launch_bounds__(256) k_stats(const int* __restrict__ pairs,
                                               const float* __restrict__ emb) {
    int row = blockIdx.x * 8 + (threadIdx.x >> 5);
    if (row >= ROWS) return;
    int lane = threadIdx.x & 31;
    int p = row & (BPAIRS - 1), side = row >> 11;
    int li = pairs[2 * p], ri = pairs[2 * p + 1];
    int node = side ? ri : li;
    const float4* a4 = (const float4*)(emb + (size_t)node * DIM);
    const float4* S4 = (const float4*)g_S;
    const float4* T4 = (const float4*)g_T;
    float v = 0.f, wv = 0.f;
    #pragma unroll
    for (int i = lane; i < DIM / 4; i += 32) {
        float4 a = a4[i], s = S4[i], t = T4[i];
        v  += a.x*s.x + a.y*s.y + a.z*s.z + a.w*s.w;
        wv += a.x*t.x + a.y*t.y + a.z*t.z + a.w*t.w;
    }
    #pragma unroll
    for (int o = 16; o; o >>= 1) {
        v  += __shfl_xor_sync(0xffffffffu, v, o);
        wv += __shfl_xor_sync(0xffffffffu, wv, o);
    }
    if (lane == 0) {
        double N = (double)NODES;
        double pos = (double)g_pos[p], asq = (double)g_asq[row];
        double Q = g_Q, Q2 = g_Q2;
        double q = (double)g_qrow[row];
        double C = pos + GAMMA_ - asq;
        double SumX  = N * C - Q + 2.0 * (double)v;
        double mu    = (SumX - pos - 2.0 * GAMMA_) / N;
        double SumX2 = N*C*C - 2.0*C*Q + Q2 + 4.0*C*(double)v - 4.0*(double)wv
                       + 4.0*q;
        double E2 = SumX2;
        if (li != ri) {
            double xl = pos + GAMMA_;
            E2 -= xl * xl + GAMMA_ * GAMMA_;
        }
        double var = E2 / N - mu * mu;
        double sd  = sqrt(fmax(var, 1e-30));
        g_cb[row]   = (float)C;
        g_rsig[row] = (float)(LAMB_ / sd);
        g_zb[row]   = (float)(TAU_ - (double)KS_ - LAMB_ * mu / sd);
    }
}

// ---------------- main GEMM + online exp (3-stage) -------------------------------
__global__ void __launch_bounds__(256, 2) k_main(const int* __restrict__ pairs) {
    extern __shared__ __align__(1024) char dsm[];
    __shared__ float s_esq[BN], s_cb[BM], s_rsig[BM], s_zb[BM];
    __shared__ int   s_l[BM], s_r[BM];
    const int tid = threadIdx.x, lane = tid & 31, w = tid >> 5;
    const int m0 = blockIdx.x * BM, n0 = blockIdx.y * BN;
    const uint32_t smb = cvta_smem(dsm);

    if (tid < BM) {
        int row = m0 + tid;
        s_cb[tid] = g_cb[row]; s_rsig[tid] = g_rsig[row]; s_zb[tid] = g_zb[row];
        int p = row & (BPAIRS - 1);
        s_l[tid] = pairs[2 * p]; s_r[tid] = pairs[2 * p + 1];
        int col = n0 + tid;
        s_esq[tid] = (col < NODES) ? g_esq[col] : 0.f;
    }

    const int wm = (w >> 1) * 32, wn = (w & 1) * 64;
    const uint32_t aRow  = (uint32_t)(lane & 15);
    const uint32_t aColB = (uint32_t)((lane >> 4) * 16);
    const uint32_t grp   = (uint32_t)(lane >> 3);
    const uint32_t bRow  = (uint32_t)((lane & 7) + ((grp >> 1) * 8));
    const uint32_t bColB = (uint32_t)((grp & 1) * 16);

    float acc[2][8][4];
    #pragma unroll
    for (int mi = 0; mi < 2; mi++)
        #pragma unroll
        for (int ni = 0; ni < 8; ni++)
            #pragma unroll
            for (int q = 0; q < 4; q++) acc[mi][ni][q] = 0.f;

    auto load_chunk = [&](int c, int st) {
        uint32_t sb = smb + (uint32_t)st * STAGE_BYTES;
        #pragma unroll
        for (int i = 0; i < 4; i++) {
            int idx = tid + 256 * i, r = idx >> 3, seg = idx & 7;
            cpasync16(sb + swz((uint32_t)(r * 128 + seg * 16)),
                      g_Ab + (size_t)(m0 + r) * DIM + c * BK + seg * 8);
        }
        #pragma unroll
        for (int i = 0; i < 4; i++) {
            int idx = tid + 256 * i, r = idx >> 3, seg = idx & 7;
            cpasync16(sb + 16384u + swz((uint32_t)(r * 128 + seg * 16)),
                      g_Eb + (size_t)(n0 + r) * DIM + c * BK + seg * 8);
        }
        COMMIT();
    };

    load_chunk(0, 0);
    load_chunk(1, 1);
    int st_next = 2, st_cur = 0;
    for (int c = 0; c < NCHUNK; c++) {
        if (c < NCHUNK - 1) WAIT1(); else WAIT0();
        __syncthreads();
        if (c + 2 < NCHUNK) {
            load_chunk(c + 2, st_next);
            if (++st_next == 3) st_next = 0;
        }
        uint32_t sA = smb + (uint32_t)st_cur * STAGE_BYTES, sB = sA + 16384u;
        if (++st_cur == 3) st_cur = 0;
        #pragma unroll
        for (int kk = 0; kk < 4; kk++) {
            uint32_t a[2][4];
            #pragma unroll
            for (int mi = 0; mi < 2; mi++)
                ldsm_x4(a[mi], sA + swz((uint32_t)((wm + mi*16 + aRow)*128 + kk*32 + aColB)));
            uint32_t b[4][4];
            #pragma unroll
            for (int nt = 0; nt < 4; nt++)
                ldsm_x4(b[nt], sB + swz((uint32_t)((wn + nt*16 + bRow)*128 + kk*32 + bColB)));
            #pragma unroll
            for (int mi = 0; mi < 2; mi++)
                #pragma unroll
                for (int nt = 0; nt < 4; nt++) {
                    mma16816(acc[mi][nt*2+0], a[mi], &b[nt][0]);
                    mma16816(acc[mi][nt*2+1], a[mi], &b[nt][2]);
                }
        }
    }

    const int qr = lane >> 2, qc = lane & 3;
    #pragma unroll
    for (int mi = 0; mi < 2; mi++) {
        #pragma unroll
        for (int h = 0; h < 2; h++) {
            int rl  = wm + mi * 16 + h * 8 + qr;
            int row = m0 + rl;
            float cb = s_cb[rl], rsig = s_rsig[rl], zb = s_zb[rl];
            int li = s_l[rl], ri = s_r[rl];
            float psum = 0.f;
            #pragma unroll
            for (int ni = 0; ni < 8; ni++) {
                int tc0 = wn + ni * 8 + qc * 2;
                int col0 = n0 + tc0;
                float x0 = cb - s_esq[tc0]     + 2.f * acc[mi][ni][h*2+0];
                float x1 = cb - s_esq[tc0 + 1] + 2.f * acc[mi][ni][h*2+1];
                x0 *= 1.f - (float)(col0 == li)     - (float)(col0 == ri);
                x1 *= 1.f - (float)(col0 + 1 == li) - (float)(col0 + 1 == ri);
                if (col0 < NODES)
                    psum += __expf(fmaf(rsig, x0, zb)) + __expf(fmaf(rsig, x1, zb));
            }
            #pragma unroll
            for (int o = 1; o < 4; o <<= 1)
                psum += __shfl_xor_sync(0xffffffffu, psum, o);
            if (qc == 0) atomicAdd(&g_sumexp[row], psum);
        }
    }
}

// ---------------- finalize --------------------------------------------------------
__global__ void k_final(float* __restrict__ out) {
    __shared__ float red[32];
    float t = 0.f;
    for (int row = threadIdx.x; row < ROWS; row += 1024)
        t += logf(g_sumexp[row]) + KS_;
    int lane = threadIdx.x & 31, wd = threadIdx.x >> 5;
    #pragma unroll
    for (int o = 16; o; o >>= 1) t += __shfl_xor_sync(0xffffffffu, t, o);
    if (lane == 0) red[wd] = t;
    __syncthreads();
    if (threadIdx.x < 32) {
        float v = red[threadIdx.x];
        #pragma unroll
        for (int o = 16; o; o >>= 1) v += __shfl_xor_sync(0xffffffffu, v, o);
        if (threadIdx.x == 0) out[0] = v * (1.f / BPAIRS);
    }
}

// ---------------- launch -----------------------------------------------------------
extern "C" void kernel_launch(void* const* d_in, const int* in_sizes, int n_in,
                              void* d_out, int out_size) {
    const int* pairs; const float* emb;
    if (in_sizes[0] == 2 * BPAIRS) { pairs = (const int*)d_in[0]; emb = (const float*)d_in[1]; }
    else                           { pairs = (const int*)d_in[1]; emb = (const float*)d_in[0]; }
    float* out = (float*)d_out;

    const int PREP_SMEM = 32 * PR_STRIDE * 4;
    cudaFuncSetAttribute(k_prep, cudaFuncAttributeMaxDynamicSharedMemorySize, PREP_SMEM);
    cudaFuncSetAttribute(k_gram, cudaFuncAttributeMaxDynamicSharedMemorySize, 3 * STAGE_BYTES);
    cudaFuncSetAttribute(k_ug,   cudaFuncAttributeMaxDynamicSharedMemorySize, 3 * 65536);
    cudaFuncSetAttribute(k_main, cudaFuncAttributeMaxDynamicSharedMemorySize, 3 * STAGE_BYTES);

    k_zero<<<(DIM * DIM + 255) / 256, 256>>>();
    k_prep<<<NODES / 32, 256, PREP_SMEM>>>(emb);
    k_gather<<<ROWS / 8, 256>>>(pairs, emb);
    k_pos<<<BPAIRS / 8, 256>>>(pairs, emb);

    dim3 gg(DIM / BM, DIM / BN, 23);
    k_gram<<<gg, 256, 3 * STAGE_BYTES>>>();
    k_gcvt<<<(DIM * DIM + 255) / 256, 256>>>();

    dim3 gu(ROWS / BM, DIM / BN);
    k_ug<<<gu, 256, 3 * 65536>>>(pairs, emb);
    k_stats<<<ROWS / 8, 256>>>(pairs, emb);

    dim3 gm(ROWS / BM, NPAD / BN);
    k_main<<<gm, 256, 3 * STAGE_BYTES>>>(pairs);

    k_final<<<1, 1024>>>(out);
}

// round 14
// speedup vs baseline: 1.0681x; 1.0681x over previous
#include <cuda_runtime.h>
#include <cuda_bf16.h>
#include <math.h>
#include <stdint.h>

#define NODES  100000
#define NPAD   100096
#define DIM    512
#define BPAIRS 2048
#define ROWS   4096
#define GAMMA_ 3.0
#define LAMB_  20.0
#define TAU_   8.0
#define KS_    90.0f

#define BM 128
#define BN 128
#define BK 64
#define NCHUNK (DIM / BK)
#define STAGE_BYTES 32768
#define PR_STRIDE 516

// ---------------- scratch ----------------------------------------------------
__device__ __align__(256) __nv_bfloat16 g_Ab[(size_t)ROWS * DIM];
__device__ __align__(256) __nv_bfloat16 g_Al[(size_t)ROWS * DIM];
__device__ __align__(256) __nv_bfloat16 g_Eb[(size_t)NPAD * DIM];
__device__ __align__(256) __nv_bfloat16 g_ET[(size_t)DIM * NPAD];
__device__ __align__(256) float g_G [(size_t)DIM * DIM];
__device__ __align__(256) __nv_bfloat16 g_Gh[(size_t)DIM * DIM];
__device__ __align__(256) __nv_bfloat16 g_Gl[(size_t)DIM * DIM];
__device__ float  g_S[DIM], g_T[DIM];
__device__ double g_Q, g_Q2;
__device__ float g_asq[ROWS], g_pos[BPAIRS], g_esq[NODES];
__device__ float g_qrow[ROWS];
__device__ float g_sumexp[ROWS], g_cb[ROWS], g_rsig[ROWS], g_zb[ROWS];

// ---------------- PTX helpers --------------------------------------------------
__device__ __forceinline__ uint32_t cvta_smem(const void* p) {
    uint32_t a;
    asm("{ .reg .u64 t; cvta.to.shared.u64 t, %1; cvt.u32.u64 %0, t; }" : "=r"(a) : "l"(p));
    return a;
}
__device__ __forceinline__ void cpasync16(uint32_t s, const void* g) {
    asm volatile("cp.async.cg.shared.global [%0], [%1], 16;" :: "r"(s), "l"(g));
}
__device__ __forceinline__ uint32_t swz(uint32_t off) { return off ^ ((off >> 3) & 0x70); }
__device__ __forceinline__ void ldsm_x4(uint32_t* r, uint32_t addr) {
    asm volatile("ldmatrix.sync.aligned.m8n8.x4.shared.b16 {%0,%1,%2,%3}, [%4];"
                 : "=r"(r[0]), "=r"(r[1]), "=r"(r[2]), "=r"(r[3]) : "r"(addr));
}
__device__ __forceinline__ void mma16816(float* c, const uint32_t* a, const uint32_t* b) {
    asm volatile(
        "mma.sync.aligned.m16n8k16.row.col.f32.bf16.bf16.f32 "
        "{%0,%1,%2,%3}, {%4,%5,%6,%7}, {%8,%9}, {%0,%1,%2,%3};"
        : "+f"(c[0]), "+f"(c[1]), "+f"(c[2]), "+f"(c[3])
        : "r"(a[0]), "r"(a[1]), "r"(a[2]), "r"(a[3]), "r"(b[0]), "r"(b[1]));
}

// ---------------- zero ----------------------------------------------------------
__global__ void k_zero() {
    int i = blockIdx.x * blockDim.x + threadIdx.x;
    if (i < DIM * DIM) g_G[i] = 0.f;
    if (i < ROWS) { g_sumexp[i] = 0.f; g_qrow[i] = 0.f; }
    if (i < DIM) { g_S[i] = 0.f; g_T[i] = 0.f; }
    if (i == 0) { g_Q = 0.0; g_Q2 = 0.0; }
}

// ---------------- fused prep (one pass over emb) --------------------------------
__global__ void __launch_bounds__(256) k_prep(const float* __restrict__ emb) {
    extern __shared__ float sm[];
    __shared__ float s_esq[32];
    const int tid = threadIdx.x;
    const int n0  = blockIdx.x * 32;
    const int w = tid >> 5, lane = tid & 31;

    #pragma unroll
    for (int i = 0; i < 16; i++) {
        int idx = tid + i * 256;
        int r = idx >> 7, c4 = idx & 127;
        float4 v = ((const float4*)emb)[(size_t)(n0 + r) * (DIM / 4) + c4];
        *(float4*)(sm + r * PR_STRIDE + c4 * 4) = v;
        __nv_bfloat162* q = (__nv_bfloat162*)(g_Eb + (size_t)(n0 + r) * DIM);
        q[c4 * 2 + 0] = __nv_bfloat162(__float2bfloat16_rn(v.x), __float2bfloat16_rn(v.y));
        q[c4 * 2 + 1] = __nv_bfloat162(__float2bfloat16_rn(v.z), __float2bfloat16_rn(v.w));
    }
    __syncthreads();

    #pragma unroll
    for (int q = 0; q < 4; q++) {
        int n = w * 4 + q;
        const float* row = sm + n * PR_STRIDE;
        float s = 0.f;
        #pragma unroll
        for (int i = 0; i < 4; i++) {
            float4 v = *(const float4*)(row + (lane + i * 32) * 4);
            s += v.x * v.x + v.y * v.y + v.z * v.z + v.w * v.w;
        }
        #pragma unroll
        for (int o = 16; o; o >>= 1) s += __shfl_xor_sync(0xffffffffu, s, o);
        if (lane == 0) { s_esq[n] = s; g_esq[n0 + n] = s; }
    }
    __syncthreads();

    #pragma unroll
    for (int dd = 0; dd < 2; dd++) {
        int d = tid + dd * 256;
        float sS = 0.f, sT = 0.f;
        #pragma unroll
        for (int n = 0; n < 32; n++) {
            float e = s_esq[n];
            float v = sm[n * PR_STRIDE + d];
            sS += v; sT += e * v;
        }
        atomicAdd(&g_S[d], sS);
        atomicAdd(&g_T[d], sT);
    }

    for (int d = w; d < DIM; d += 8)
        g_ET[(size_t)d * NPAD + n0 + lane] =
            __float2bfloat16_rn(sm[lane * PR_STRIDE + d]);

    if (tid < 32) {
        double e = (double)s_esq[tid], e2 = e * e;
        #pragma unroll
        for (int o = 16; o; o >>= 1) {
            e  += __shfl_xor_sync(0xffffffffu, e, o);
            e2 += __shfl_xor_sync(0xffffffffu, e2, o);
        }
        if (tid == 0) { atomicAdd(&g_Q, e); atomicAdd(&g_Q2, e2); }
    }
}

// gather A hi/lo + asq
__global__ void k_gather(const int* __restrict__ pairs, const float* __restrict__ emb) {
    int row = blockIdx.x * 8 + (threadIdx.x >> 5);
    if (row >= ROWS) return;
    int lane = threadIdx.x & 31;
    int p = row & (BPAIRS - 1), side = row >> 11;
    int node = pairs[2 * p + side];
    const float4* src = (const float4*)(emb + (size_t)node * DIM);
    float s = 0.f;
    #pragma unroll
    for (int i = lane; i < DIM / 4; i += 32) {
        float4 v = src[i];
        float f[4] = {v.x, v.y, v.z, v.w};
        __nv_bfloat16 h[4], l[4];
        #pragma unroll
        for (int q = 0; q < 4; q++) {
            h[q] = __float2bfloat16_rn(f[q]);
            l[q] = __float2bfloat16_rn(f[q] - __bfloat162float(h[q]));
            s += f[q] * f[q];
        }
        __nv_bfloat162* H = (__nv_bfloat162*)(g_Ab + (size_t)row * DIM + i * 4);
        __nv_bfloat162* L = (__nv_bfloat162*)(g_Al + (size_t)row * DIM + i * 4);
        H[0] = __nv_bfloat162(h[0], h[1]); H[1] = __nv_bfloat162(h[2], h[3]);
        L[0] = __nv_bfloat162(l[0], l[1]); L[1] = __nv_bfloat162(l[2], l[3]);
    }
    #pragma unroll
    for (int o = 16; o; o >>= 1) s += __shfl_xor_sync(0xffffffffu, s, o);
    if (lane == 0) g_asq[row] = s;
}

__global__ void k_pos(const int* __restrict__ pairs, const float* __restrict__ emb) {
    int p = blockIdx.x * 8 + (threadIdx.x >> 5);
    if (p >= BPAIRS) return;
    int lane = threadIdx.x & 31;
    int ln = pairs[2 * p], rn = pairs[2 * p + 1];
    const float4* a = (const float4*)(emb + (size_t)ln * DIM);
    const float4* b = (const float4*)(emb + (size_t)rn * DIM);
    float s = 0.f;
    #pragma unroll
    for (int i = lane; i < DIM / 4; i += 32) {
        float4 x = a[i], y = b[i];
        float dx = x.x - y.x, dy = x.y - y.y, dz = x.z - y.z, dw = x.w - y.w;
        s += dx * dx + dy * dy + dz * dz + dw * dw;
    }
    #pragma unroll
    for (int o = 16; o; o >>= 1) s += __shfl_xor_sync(0xffffffffu, s, o);
    if (lane == 0) g_pos[p] = s;
}

// ---------------- Gram G = E^T E (2-stage, symmetric-half) ----------------------
#define GZCH 68
__global__ void __launch_bounds__(256, 2) k_gram() {
    const int bx = blockIdx.x, by = blockIdx.y;
    if (by < bx) return;
    extern __shared__ __align__(1024) char dsm[];
    const int tid = threadIdx.x, lane = tid & 31, w = tid >> 5;
    const int m0 = bx * BM, n0 = by * BN;
    const uint32_t smb = cvta_smem(dsm);
    const int wm = (w >> 1) * 32, wn = (w & 1) * 64;
    const uint32_t aRow  = (uint32_t)(lane & 15);
    const uint32_t aColB = (uint32_t)((lane >> 4) * 16);
    const uint32_t grp   = (uint32_t)(lane >> 3);
    const uint32_t bRow  = (uint32_t)((lane & 7) + ((grp >> 1) * 8));
    const uint32_t bColB = (uint32_t)((grp & 1) * 16);

    float acc[2][8][4];
    #pragma unroll
    for (int mi = 0; mi < 2; mi++)
        #pragma unroll
        for (int ni = 0; ni < 8; ni++)
            #pragma unroll
            for (int q = 0; q < 4; q++) acc[mi][ni][q] = 0.f;

    const int cbase = blockIdx.z * GZCH;
    auto load_chunk = [&](int c, int st) {
        uint32_t sb = smb + (uint32_t)st * STAGE_BYTES;
        size_t node0 = (size_t)(cbase + c) * BK;
        #pragma unroll
        for (int i = 0; i < 4; i++) {
            int idx = tid + 256 * i, r = idx >> 3, seg = idx & 7;
            cpasync16(sb + swz((uint32_t)(r * 128 + seg * 16)),
                      g_ET + (size_t)(m0 + r) * NPAD + node0 + seg * 8);
        }
        #pragma unroll
        for (int i = 0; i < 4; i++) {
            int idx = tid + 256 * i, r = idx >> 3, seg = idx & 7;
            cpasync16(sb + 16384u + swz((uint32_t)(r * 128 + seg * 16)),
                      g_ET + (size_t)(n0 + r) * NPAD + node0 + seg * 8);
        }
        asm volatile("cp.async.commit_group;" ::: "memory");
    };

    load_chunk(0, 0);
    __syncthreads();
    for (int c = 0; c < GZCH; c++) {
        if (c < GZCH - 1) { load_chunk(c + 1, (c + 1) & 1);
                            asm volatile("cp.async.wait_group 1;" ::: "memory"); }
        else                asm volatile("cp.async.wait_group 0;" ::: "memory");
        __syncthreads();
        uint32_t sA = smb + (uint32_t)(c & 1) * STAGE_BYTES, sB = sA + 16384u;
        #pragma unroll
        for (int kk = 0; kk < 4; kk++) {
            uint32_t a[2][4];
            #pragma unroll
            for (int mi = 0; mi < 2; mi++)
                ldsm_x4(a[mi], sA + swz((uint32_t)((wm + mi*16 + aRow)*128 + kk*32 + aColB)));
            uint32_t b[4][4];
            #pragma unroll
            for (int nt = 0; nt < 4; nt++)
                ldsm_x4(b[nt], sB + swz((uint32_t)((wn + nt*16 + bRow)*128 + kk*32 + bColB)));
            #pragma unroll
            for (int mi = 0; mi < 2; mi++)
                #pragma unroll
                for (int nt = 0; nt < 4; nt++) {
                    mma16816(acc[mi][nt*2+0], a[mi], &b[nt][0]);
                    mma16816(acc[mi][nt*2+1], a[mi], &b[nt][2]);
                }
        }
        __syncthreads();
    }
    const int qr = lane >> 2, qc = lane & 3;
    #pragma unroll
    for (int mi = 0; mi < 2; mi++)
        #pragma unroll
        for (int h = 0; h < 2; h++) {
            int i = m0 + wm + mi * 16 + h * 8 + qr;
            #pragma unroll
            for (int ni = 0; ni < 8; ni++) {
                int j = n0 + wn + ni * 8 + qc * 2;
                float d0 = acc[mi][ni][h*2+0], d1 = acc[mi][ni][h*2+1];
                atomicAdd(&g_G[(size_t)i * DIM + j],     d0);
                atomicAdd(&g_G[(size_t)i * DIM + j + 1], d1);
                if (bx != by) {
                    atomicAdd(&g_G[(size_t)j * DIM + i],       d0);
                    atomicAdd(&g_G[(size_t)(j + 1) * DIM + i], d1);
                }
            }
        }
}

__global__ void k_gcvt() {
    int i = blockIdx.x * blockDim.x + threadIdx.x;
    if (i >= DIM * DIM) return;
    float g = g_G[i];
    __nv_bfloat16 h = __float2bfloat16_rn(g);
    g_Gh[i] = h;
    g_Gl[i] = __float2bfloat16_rn(g - __bfloat162float(h));
}

// ---------------- U = A*G, q = rowsum(U .* a) folded (2-stage) ------------------
__global__ void __launch_bounds__(256, 1) k_ug(const int* __restrict__ pairs,
                                               const float* __restrict__ emb) {
    extern __shared__ __align__(1024) char dsm[];
    const int tid = threadIdx.x, lane = tid & 31, w = tid >> 5;
    const int m0 = blockIdx.x * BM, n0 = blockIdx.y * BN;
    const uint32_t smb = cvta_smem(dsm);
    const uint32_t SS = 65536u;
    const int wm = (w >> 1) * 32, wn = (w & 1) * 64;
    const uint32_t aRow  = (uint32_t)(lane & 15);
    const uint32_t aColB = (uint32_t)((lane >> 4) * 16);
    const uint32_t grp   = (uint32_t)(lane >> 3);
    const uint32_t bRow  = (uint32_t)((lane & 7) + ((grp >> 1) * 8));
    const uint32_t bColB = (uint32_t)((grp & 1) * 16);

    float acc[2][8][4];
    #pragma unroll
    for (int mi = 0; mi < 2; mi++)
        #pragma unroll
        for (int ni = 0; ni < 8; ni++)
            #pragma unroll
            for (int q = 0; q < 4; q++) acc[mi][ni][q] = 0.f;

    auto load_chunk = [&](int c, int st) {
        uint32_t sb = smb + (uint32_t)st * SS;
        #pragma unroll
        for (int i = 0; i < 4; i++) {
            int idx = tid + 256 * i, r = idx >> 3, seg = idx & 7;
            uint32_t so = swz((uint32_t)(r * 128 + seg * 16));
            cpasync16(sb + so,          g_Ab + (size_t)(m0 + r) * DIM + c * BK + seg * 8);
            cpasync16(sb + 16384u + so, g_Al + (size_t)(m0 + r) * DIM + c * BK + seg * 8);
            cpasync16(sb + 32768u + so, g_Gh + (size_t)(n0 + r) * DIM + c * BK + seg * 8);
            cpasync16(sb + 49152u + so, g_Gl + (size_t)(n0 + r) * DIM + c * BK + seg * 8);
        }
        asm volatile("cp.async.commit_group;" ::: "memory");
    };

    load_chunk(0, 0);
    __syncthreads();
    for (int c = 0; c < NCHUNK; c++) {
        if (c < NCHUNK - 1) { load_chunk(c + 1, (c + 1) & 1);
                              asm volatile("cp.async.wait_group 1;" ::: "memory"); }
        else                  asm volatile("cp.async.wait_group 0;" ::: "memory");
        __syncthreads();
        uint32_t sb = smb + (uint32_t)(c & 1) * SS;
        #pragma unroll
        for (int kk = 0; kk < 4; kk++) {
            uint32_t ah[2][4], al[2][4];
            #pragma unroll
            for (int mi = 0; mi < 2; mi++) {
                uint32_t so = swz((uint32_t)((wm + mi*16 + aRow)*128 + kk*32 + aColB));
                ldsm_x4(ah[mi], sb + so);
                ldsm_x4(al[mi], sb + 16384u + so);
            }
            uint32_t gh[4][4], gl[4][4];
            #pragma unroll
            for (int nt = 0; nt < 4; nt++) {
                uint32_t so = swz((uint32_t)((wn + nt*16 + bRow)*128 + kk*32 + bColB));
                ldsm_x4(gh[nt], sb + 32768u + so);
                ldsm_x4(gl[nt], sb + 49152u + so);
            }
            #pragma unroll
            for (int mi = 0; mi < 2; mi++)
                #pragma unroll
                for (int nt = 0; nt < 4; nt++) {
                    mma16816(acc[mi][nt*2+0], ah[mi], &gh[nt][0]);
                    mma16816(acc[mi][nt*2+1], ah[mi], &gh[nt][2]);
                    mma16816(acc[mi][nt*2+0], ah[mi], &gl[nt][0]);
                    mma16816(acc[mi][nt*2+1], ah[mi], &gl[nt][2]);
                    mma16816(acc[mi][nt*2+0], al[mi], &gh[nt][0]);
                    mma16816(acc[mi][nt*2+1], al[mi], &gh[nt][2]);
                }
        }
        __syncthreads();
    }

    const int qr = lane >> 2, qc = lane & 3;
    #pragma unroll
    for (int mi = 0; mi < 2; mi++)
        #pragma unroll
        for (int h = 0; h < 2; h++) {
            int row = m0 + wm + mi * 16 + h * 8 + qr;
            int p = row & (BPAIRS - 1), side = row >> 11;
            int node = pairs[2 * p + side];
            const float* arow = emb + (size_t)node * DIM + n0;
            float qs = 0.f;
            #pragma unroll
            for (int ni = 0; ni < 8; ni++) {
                int col = wn + ni * 8 + qc * 2;
                qs += acc[mi][ni][h*2+0] * arow[col]
                    + acc[mi][ni][h*2+1] * arow[col + 1];
            }
            #pragma unroll
            for (int o = 1; o < 4; o <<= 1)
                qs += __shfl_xor_sync(0xffffffffu, qs, o);
            if (qc == 0) atomicAdd(&g_qrow[row], qs);
        }
}

// ---------------- per-row analytic stats ----------------------------------------
__global__ void __launch_bounds__(256) k_stats(const int* __restrict__ pairs,
                                               const float* __restrict__ emb) {
    int row = blockIdx.x * 8 + (threadIdx.x >> 5);
    if (row >= ROWS) return;
    int lane = threadIdx.x & 31;
    int p = row & (BPAIRS - 1), side = row >> 11;
    int li = pairs[2 * p], ri = pairs[2 * p + 1];
    int node = side ? ri : li;
    const float4* a4 = (const float4*)(emb + (size_t)node * DIM);
    const float4* S4 = (const float4*)g_S;
    const float4* T4 = (const float4*)g_T;
    float v = 0.f, wv = 0.f;
    #pragma unroll
    for (int i = lane; i < DIM / 4; i += 32) {
        float4 a = a4[i], s = S4[i], t = T4[i];
        v  += a.x*s.x + a.y*s.y + a.z*s.z + a.w*s.w;
        wv += a.x*t.x + a.y*t.y + a.z*t.z + a.w*t.w;
    }
    #pragma unroll
    for (int o = 16; o; o >>= 1) {
        v  += __shfl_xor_sync(0xffffffffu, v, o);
        wv += __shfl_xor_sync(0xffffffffu, wv, o);
    }
    if (lane == 0) {
        double N = (double)NODES;
        double pos = (double)g_pos[p], asq = (double)g_asq[row];
        double Q = g_Q, Q2 = g_Q2;
        double q = (double)g_qrow[row];
        double C = pos + GAMMA_ - asq;
        double SumX  = N * C - Q + 2.0 * (double)v;
        double mu    = (SumX - pos - 2.0 * GAMMA_) / N;
        double SumX2 = N*C*C - 2.0*C*Q + Q2 + 4.0*C*(double)v - 4.0*(double)wv
                       + 4.0*q;
        double E2 = SumX2;
        if (li != ri) {
            double xl = pos + GAMMA_;
            E2 -= xl * xl + GAMMA_ * GAMMA_;
        }
        double var = E2 / N - mu * mu;
        double sd  = sqrt(fmax(var, 1e-30));
        g_cb[row]   = (float)C;
        g_rsig[row] = (float)(LAMB_ / sd);
        g_zb[row]   = (float)(TAU_ - (double)KS_ - LAMB_ * mu / sd);
    }
}

// ---------------- main GEMM + gated online exp (2-stage) -------------------------
__global__ void __launch_bounds__(256, 2) k_main(const int* __restrict__ pairs) {
    extern __shared__ __align__(1024) char dsm[];
    __shared__ float s_esq[BN], s_cb[BM], s_rsig[BM], s_zb[BM];
    __shared__ int   s_l[BM], s_r[BM];
    const int tid = threadIdx.x, lane = tid & 31, w = tid >> 5;
    const int m0 = blockIdx.x * BM, n0 = blockIdx.y * BN;
    const uint32_t smb = cvta_smem(dsm);

    if (tid < BM) {
        int row = m0 + tid;
        s_cb[tid] = g_cb[row]; s_rsig[tid] = g_rsig[row]; s_zb[tid] = g_zb[row];
        int p = row & (BPAIRS - 1);
        s_l[tid] = pairs[2 * p]; s_r[tid] = pairs[2 * p + 1];
        int col = n0 + tid;
        s_esq[tid] = (col < NODES) ? g_esq[col] : 0.f;
    }

    const int wm = (w >> 1) * 32, wn = (w & 1) * 64;
    const uint32_t aRow  = (uint32_t)(lane & 15);
    const uint32_t aColB = (uint32_t)((lane >> 4) * 16);
    const uint32_t grp   = (uint32_t)(lane >> 3);
    const uint32_t bRow  = (uint32_t)((lane & 7) + ((grp >> 1) * 8));
    const uint32_t bColB = (uint32_t)((grp & 1) * 16);

    float acc[2][8][4];
    #pragma unroll
    for (int mi = 0; mi < 2; mi++)
        #pragma unroll
        for (int ni = 0; ni < 8; ni++)
            #pragma unroll
            for (int q = 0; q < 4; q++) acc[mi][ni][q] = 0.f;

    auto load_chunk = [&](int c, int st) {
        uint32_t sb = smb + (uint32_t)st * STAGE_BYTES;
        #pragma unroll
        for (int i = 0; i < 4; i++) {
            int idx = tid + 256 * i, r = idx >> 3, seg = idx & 7;
            cpasync16(sb + swz((uint32_t)(r * 128 + seg * 16)),
                      g_Ab + (size_t)(m0 + r) * DIM + c * BK + seg * 8);
        }
        #pragma unroll
        for (int i = 0; i < 4; i++) {
            int idx = tid + 256 * i, r = idx >> 3, seg = idx & 7;
            cpasync16(sb + 16384u + swz((uint32_t)(r * 128 + seg * 16)),
                      g_Eb + (size_t)(n0 + r) * DIM + c * BK + seg * 8);
        }
        asm volatile("cp.async.commit_group;" ::: "memory");
    };

    load_chunk(0, 0);
    __syncthreads();
    for (int c = 0; c < NCHUNK; c++) {
        if (c < NCHUNK - 1) { load_chunk(c + 1, (c + 1) & 1);
                              asm volatile("cp.async.wait_group 1;" ::: "memory"); }
        else                  asm volatile("cp.async.wait_group 0;" ::: "memory");
        __syncthreads();
        uint32_t sA = smb + (uint32_t)(c & 1) * STAGE_BYTES, sB = sA + 16384u;
        #pragma unroll
        for (int kk = 0; kk < 4; kk++) {
            uint32_t a[2][4];
            #pragma unroll
            for (int mi = 0; mi < 2; mi++)
                ldsm_x4(a[mi], sA + swz((uint32_t)((wm + mi*16 + aRow)*128 + kk*32 + aColB)));
            uint32_t b[4][4];
            #pragma unroll
            for (int nt = 0; nt < 4; nt++)
                ldsm_x4(b[nt], sB + swz((uint32_t)((wn + nt*16 + bRow)*128 + kk*32 + bColB)));
            #pragma unroll
            for (int mi = 0; mi < 2; mi++)
                #pragma unroll
                for (int nt = 0; nt < 4; nt++) {
                    mma16816(acc[mi][nt*2+0], a[mi], &b[nt][0]);
                    mma16816(acc[mi][nt*2+1], a[mi], &b[nt][2]);
                }
        }
        __syncthreads();
    }

    // ---- gated exp epilogue: only ~0.2% of entries have exponent > -25 ----
    const int qr = lane >> 2, qc = lane & 3;
    #pragma unroll
    for (int mi = 0; mi < 2; mi++) {
        #pragma unroll
        for (int h = 0; h < 2; h++) {
            int rl  = wm + mi * 16 + h * 8 + qr;
            int row = m0 + rl;
            float cb = s_cb[rl], rsig = s_rsig[rl], zb = s_zb[rl];
            int li = s_l[rl], ri = s_r[rl];
            float psum = 0.f;
            #pragma unroll
            for (int ni = 0; ni < 8; ni++) {
                int tc0 = wn + ni * 8 + qc * 2;
                int col0 = n0 + tc0;
                float x0 = cb - s_esq[tc0]     + 2.f * acc[mi][ni][h*2+0];
                float x1 = cb - s_esq[tc0 + 1] + 2.f * acc[mi][ni][h*2+1];
                x0 *= 1.f - (float)(col0 == li)     - (float)(col0 == ri);
                x1 *= 1.f - (float)(col0 + 1 == li) - (float)(col0 + 1 == ri);
                float e0 = fmaf(rsig, x0, zb);
                float e1 = fmaf(rsig, x1, zb);
                if (col0 >= NODES) { e0 = -100.f; e1 = -100.f; }
                bool sig = fmaxf(e0, e1) > -25.f;
                if (__any_sync(0xffffffffu, sig))
                    psum += __expf(e0) + __expf(e1);
            }
            #pragma unroll
            for (int o = 1; o < 4; o <<= 1)
                psum += __shfl_xor_sync(0xffffffffu, psum, o);
            if (qc == 0 && psum != 0.f) atomicAdd(&g_sumexp[row], psum);
        }
    }
}

// ---------------- finalize --------------------------------------------------------
__global__ void k_final(float* __restrict__ out) {
    __shared__ float red[32];
    float t = 0.f;
    for (int row = threadIdx.x; row < ROWS; row += 1024)
        t += logf(g_sumexp[row]) + KS_;
    int lane = threadIdx.x & 31, wd = threadIdx.x >> 5;
    #pragma unroll
    for (int o = 16; o; o >>= 1) t += __shfl_xor_sync(0xffffffffu, t, o);
    if (lane == 0) red[wd] = t;
    __syncthreads();
    if (threadIdx.x < 32) {
        float v = red[threadIdx.x];
        #pragma unroll
        for (int o = 16; o; o >>= 1) v += __shfl_xor_sync(0xffffffffu, v, o);
        if (threadIdx.x == 0) out[0] = v * (1.f / BPAIRS);
    }
}

// ---------------- launch -----------------------------------------------------------
extern "C" void kernel_launch(void* const* d_in, const int* in_sizes, int n_in,
                              void* d_out, int out_size) {
    const int* pairs; const float* emb;
    if (in_sizes[0] == 2 * BPAIRS) { pairs = (const int*)d_in[0]; emb = (const float*)d_in[1]; }
    else                           { pairs = (const int*)d_in[1]; emb = (const float*)d_in[0]; }
    float* out = (float*)d_out;

    const int PREP_SMEM = 32 * PR_STRIDE * 4;
    cudaFuncSetAttribute(k_prep, cudaFuncAttributeMaxDynamicSharedMemorySize, PREP_SMEM);
    cudaFuncSetAttribute(k_gram, cudaFuncAttributeMaxDynamicSharedMemorySize, 65536);
    cudaFuncSetAttribute(k_ug,   cudaFuncAttributeMaxDynamicSharedMemorySize, 131072);
    cudaFuncSetAttribute(k_main, cudaFuncAttributeMaxDynamicSharedMemorySize, 65536);

    k_zero<<<(DIM * DIM + 255) / 256, 256>>>();
    k_prep<<<NODES / 32, 256, PREP_SMEM>>>(emb);
    k_gather<<<ROWS / 8, 256>>>(pairs, emb);
    k_pos<<<BPAIRS / 8, 256>>>(pairs, emb);

    dim3 gg(DIM / BM, DIM / BN, 23);
    k_gram<<<gg, 256, 65536>>>();
    k_gcvt<<<(DIM * DIM + 255) / 256, 256>>>();

    dim3 gu(ROWS / BM, DIM / BN);
    k_ug<<<gu, 256, 131072>>>(pairs, emb);
    k_stats<<<ROWS / 8, 256>>>(pairs, emb);

    dim3 gm(ROWS / BM, NPAD / BN);
    k_main<<<gm, 256, 65536>>>(pairs);

    k_final<<<1, 1024>>>(out);
}

// round 15
// speedup vs baseline: 1.1297x; 1.0576x over previous
#include <cuda_runtime.h>
#include <cuda_bf16.h>
#include <math.h>
#include <stdint.h>

#define NODES  100000
#define NPAD   100096
#define DIM    512
#define BPAIRS 2048
#define ROWS   4096
#define GAMMA_ 3.0
#define LAMB_  20.0
#define TAU_   8.0
#define KS_    90.0f

#define BM 128
#define BN 128
#define BK 64
#define NCHUNK (DIM / BK)
#define STAGE_BYTES 32768
#define UG_STAGE 49152
#define PR_STRIDE 516

// ---------------- scratch ----------------------------------------------------
__device__ __align__(256) __nv_bfloat16 g_Ab[(size_t)ROWS * DIM];
__device__ __align__(256) __nv_bfloat16 g_Al[(size_t)ROWS * DIM];
__device__ __align__(256) __nv_bfloat16 g_Eb[(size_t)NPAD * DIM];
__device__ __align__(256) __nv_bfloat16 g_ET[(size_t)DIM * NPAD];
__device__ __align__(256) float g_G [(size_t)DIM * DIM];
__device__ __align__(256) __nv_bfloat16 g_Gh[(size_t)DIM * DIM];
__device__ float  g_S[DIM], g_T[DIM];
__device__ double g_Q, g_Q2;
__device__ float g_asq[ROWS], g_pos[BPAIRS], g_esq[NODES];
__device__ float g_qrow[ROWS];
__device__ float g_sumexp[ROWS], g_cb[ROWS], g_rsig[ROWS], g_zb[ROWS];

// ---------------- PTX helpers --------------------------------------------------
__device__ __forceinline__ uint32_t cvta_smem(const void* p) {
    uint32_t a;
    asm("{ .reg .u64 t; cvta.to.shared.u64 t, %1; cvt.u32.u64 %0, t; }" : "=r"(a) : "l"(p));
    return a;
}
__device__ __forceinline__ void cpasync16(uint32_t s, const void* g) {
    asm volatile("cp.async.cg.shared.global [%0], [%1], 16;" :: "r"(s), "l"(g));
}
__device__ __forceinline__ uint32_t swz(uint32_t off) { return off ^ ((off >> 3) & 0x70); }
__device__ __forceinline__ void ldsm_x4(uint32_t* r, uint32_t addr) {
    asm volatile("ldmatrix.sync.aligned.m8n8.x4.shared.b16 {%0,%1,%2,%3}, [%4];"
                 : "=r"(r[0]), "=r"(r[1]), "=r"(r[2]), "=r"(r[3]) : "r"(addr));
}
__device__ __forceinline__ void mma16816(float* c, const uint32_t* a, const uint32_t* b) {
    asm volatile(
        "mma.sync.aligned.m16n8k16.row.col.f32.bf16.bf16.f32 "
        "{%0,%1,%2,%3}, {%4,%5,%6,%7}, {%8,%9}, {%0,%1,%2,%3};"
        : "+f"(c[0]), "+f"(c[1]), "+f"(c[2]), "+f"(c[3])
        : "r"(a[0]), "r"(a[1]), "r"(a[2]), "r"(a[3]), "r"(b[0]), "r"(b[1]));
}
#define WAIT1() asm volatile("cp.async.wait_group 1;" ::: "memory")
#define WAIT0() asm volatile("cp.async.wait_group 0;" ::: "memory")
#define COMMIT() asm volatile("cp.async.commit_group;" ::: "memory")

// ---------------- zero ----------------------------------------------------------
__global__ void k_zero() {
    int i = blockIdx.x * blockDim.x + threadIdx.x;
    if (i < DIM * DIM) g_G[i] = 0.f;
    if (i < ROWS) { g_sumexp[i] = 0.f; g_qrow[i] = 0.f; }
    if (i < DIM) { g_S[i] = 0.f; g_T[i] = 0.f; }
    if (i == 0) { g_Q = 0.0; g_Q2 = 0.0; }
}

// ---------------- fused prep (one pass over emb) --------------------------------
__global__ void __launch_bounds__(256) k_prep(const float* __restrict__ emb) {
    extern __shared__ float sm[];
    __shared__ float s_esq[32];
    const int tid = threadIdx.x;
    const int n0  = blockIdx.x * 32;
    const int w = tid >> 5, lane = tid & 31;

    #pragma unroll
    for (int i = 0; i < 16; i++) {
        int idx = tid + i * 256;
        int r = idx >> 7, c4 = idx & 127;
        float4 v = ((const float4*)emb)[(size_t)(n0 + r) * (DIM / 4) + c4];
        *(float4*)(sm + r * PR_STRIDE + c4 * 4) = v;
        __nv_bfloat162* q = (__nv_bfloat162*)(g_Eb + (size_t)(n0 + r) * DIM);
        q[c4 * 2 + 0] = __nv_bfloat162(__float2bfloat16_rn(v.x), __float2bfloat16_rn(v.y));
        q[c4 * 2 + 1] = __nv_bfloat162(__float2bfloat16_rn(v.z), __float2bfloat16_rn(v.w));
    }
    __syncthreads();

    #pragma unroll
    for (int q = 0; q < 4; q++) {
        int n = w * 4 + q;
        const float* row = sm + n * PR_STRIDE;
        float s = 0.f;
        #pragma unroll
        for (int i = 0; i < 4; i++) {
            float4 v = *(const float4*)(row + (lane + i * 32) * 4);
            s += v.x * v.x + v.y * v.y + v.z * v.z + v.w * v.w;
        }
        #pragma unroll
        for (int o = 16; o; o >>= 1) s += __shfl_xor_sync(0xffffffffu, s, o);
        if (lane == 0) { s_esq[n] = s; g_esq[n0 + n] = s; }
    }
    __syncthreads();

    #pragma unroll
    for (int dd = 0; dd < 2; dd++) {
        int d = tid + dd * 256;
        float sS = 0.f, sT = 0.f;
        #pragma unroll
        for (int n = 0; n < 32; n++) {
            float e = s_esq[n];
            float v = sm[n * PR_STRIDE + d];
            sS += v; sT += e * v;
        }
        atomicAdd(&g_S[d], sS);
        atomicAdd(&g_T[d], sT);
    }

    for (int d = w; d < DIM; d += 8)
        g_ET[(size_t)d * NPAD + n0 + lane] =
            __float2bfloat16_rn(sm[lane * PR_STRIDE + d]);

    if (tid < 32) {
        double e = (double)s_esq[tid], e2 = e * e;
        #pragma unroll
        for (int o = 16; o; o >>= 1) {
            e  += __shfl_xor_sync(0xffffffffu, e, o);
            e2 += __shfl_xor_sync(0xffffffffu, e2, o);
        }
        if (tid == 0) { atomicAdd(&g_Q, e); atomicAdd(&g_Q2, e2); }
    }
}

// gather A hi/lo + asq
__global__ void k_gather(const int* __restrict__ pairs, const float* __restrict__ emb) {
    int row = blockIdx.x * 8 + (threadIdx.x >> 5);
    if (row >= ROWS) return;
    int lane = threadIdx.x & 31;
    int p = row & (BPAIRS - 1), side = row >> 11;
    int node = pairs[2 * p + side];
    const float4* src = (const float4*)(emb + (size_t)node * DIM);
    float s = 0.f;
    #pragma unroll
    for (int i = lane; i < DIM / 4; i += 32) {
        float4 v = src[i];
        float f[4] = {v.x, v.y, v.z, v.w};
        __nv_bfloat16 h[4], l[4];
        #pragma unroll
        for (int q = 0; q < 4; q++) {
            h[q] = __float2bfloat16_rn(f[q]);
            l[q] = __float2bfloat16_rn(f[q] - __bfloat162float(h[q]));
            s += f[q] * f[q];
        }
        __nv_bfloat162* H = (__nv_bfloat162*)(g_Ab + (size_t)row * DIM + i * 4);
        __nv_bfloat162* L = (__nv_bfloat162*)(g_Al + (size_t)row * DIM + i * 4);
        H[0] = __nv_bfloat162(h[0], h[1]); H[1] = __nv_bfloat162(h[2], h[3]);
        L[0] = __nv_bfloat162(l[0], l[1]); L[1] = __nv_bfloat162(l[2], l[3]);
    }
    #pragma unroll
    for (int o = 16; o; o >>= 1) s += __shfl_xor_sync(0xffffffffu, s, o);
    if (lane == 0) g_asq[row] = s;
}

__global__ void k_pos(const int* __restrict__ pairs, const float* __restrict__ emb) {
    int p = blockIdx.x * 8 + (threadIdx.x >> 5);
    if (p >= BPAIRS) return;
    int lane = threadIdx.x & 31;
    int ln = pairs[2 * p], rn = pairs[2 * p + 1];
    const float4* a = (const float4*)(emb + (size_t)ln * DIM);
    const float4* b = (const float4*)(emb + (size_t)rn * DIM);
    float s = 0.f;
    #pragma unroll
    for (int i = lane; i < DIM / 4; i += 32) {
        float4 x = a[i], y = b[i];
        float dx = x.x - y.x, dy = x.y - y.y, dz = x.z - y.z, dw = x.w - y.w;
        s += dx * dx + dy * dy + dz * dz + dw * dw;
    }
    #pragma unroll
    for (int o = 16; o; o >>= 1) s += __shfl_xor_sync(0xffffffffu, s, o);
    if (lane == 0) g_pos[p] = s;
}

// ---------------- Gram G = E^T E (2-stage, symmetric-half) ----------------------
#define GZCH 68
__global__ void __launch_bounds__(256, 2) k_gram() {
    const int bx = blockIdx.x, by = blockIdx.y;
    if (by < bx) return;
    extern __shared__ __align__(1024) char dsm[];
    const int tid = threadIdx.x, lane = tid & 31, w = tid >> 5;
    const int m0 = bx * BM, n0 = by * BN;
    const uint32_t smb = cvta_smem(dsm);
    const int wm = (w >> 1) * 32, wn = (w & 1) * 64;
    const uint32_t aRow  = (uint32_t)(lane & 15);
    const uint32_t aColB = (uint32_t)((lane >> 4) * 16);
    const uint32_t grp   = (uint32_t)(lane >> 3);
    const uint32_t bRow  = (uint32_t)((lane & 7) + ((grp >> 1) * 8));
    const uint32_t bColB = (uint32_t)((grp & 1) * 16);

    float acc[2][8][4];
    #pragma unroll
    for (int mi = 0; mi < 2; mi++)
        #pragma unroll
        for (int ni = 0; ni < 8; ni++)
            #pragma unroll
            for (int q = 0; q < 4; q++) acc[mi][ni][q] = 0.f;

    const int cbase = blockIdx.z * GZCH;
    auto load_chunk = [&](int c, int st) {
        uint32_t sb = smb + (uint32_t)st * STAGE_BYTES;
        size_t node0 = (size_t)(cbase + c) * BK;
        #pragma unroll
        for (int i = 0; i < 4; i++) {
            int idx = tid + 256 * i, r = idx >> 3, seg = idx & 7;
            cpasync16(sb + swz((uint32_t)(r * 128 + seg * 16)),
                      g_ET + (size_t)(m0 + r) * NPAD + node0 + seg * 8);
        }
        #pragma unroll
        for (int i = 0; i < 4; i++) {
            int idx = tid + 256 * i, r = idx >> 3, seg = idx & 7;
            cpasync16(sb + 16384u + swz((uint32_t)(r * 128 + seg * 16)),
                      g_ET + (size_t)(n0 + r) * NPAD + node0 + seg * 8);
        }
        COMMIT();
    };

    load_chunk(0, 0);
    __syncthreads();
    for (int c = 0; c < GZCH; c++) {
        if (c < GZCH - 1) { load_chunk(c + 1, (c + 1) & 1); WAIT1(); }
        else               WAIT0();
        __syncthreads();
        uint32_t sA = smb + (uint32_t)(c & 1) * STAGE_BYTES, sB = sA + 16384u;
        #pragma unroll
        for (int kk = 0; kk < 4; kk++) {
            uint32_t a[2][4];
            #pragma unroll
            for (int mi = 0; mi < 2; mi++)
                ldsm_x4(a[mi], sA + swz((uint32_t)((wm + mi*16 + aRow)*128 + kk*32 + aColB)));
            uint32_t b[4][4];
            #pragma unroll
            for (int nt = 0; nt < 4; nt++)
                ldsm_x4(b[nt], sB + swz((uint32_t)((wn + nt*16 + bRow)*128 + kk*32 + bColB)));
            #pragma unroll
            for (int mi = 0; mi < 2; mi++)
                #pragma unroll
                for (int nt = 0; nt < 4; nt++) {
                    mma16816(acc[mi][nt*2+0], a[mi], &b[nt][0]);
                    mma16816(acc[mi][nt*2+1], a[mi], &b[nt][2]);
                }
        }
        __syncthreads();
    }
    const int qr = lane >> 2, qc = lane & 3;
    #pragma unroll
    for (int mi = 0; mi < 2; mi++)
        #pragma unroll
        for (int h = 0; h < 2; h++) {
            int i = m0 + wm + mi * 16 + h * 8 + qr;
            #pragma unroll
            for (int ni = 0; ni < 8; ni++) {
                int j = n0 + wn + ni * 8 + qc * 2;
                float d0 = acc[mi][ni][h*2+0], d1 = acc[mi][ni][h*2+1];
                atomicAdd(&g_G[(size_t)i * DIM + j],     d0);
                atomicAdd(&g_G[(size_t)i * DIM + j + 1], d1);
                if (bx != by) {
                    atomicAdd(&g_G[(size_t)j * DIM + i],       d0);
                    atomicAdd(&g_G[(size_t)(j + 1) * DIM + i], d1);
                }
            }
        }
}

__global__ void k_gcvt() {
    int i = blockIdx.x * blockDim.x + threadIdx.x;
    if (i >= DIM * DIM) return;
    g_Gh[i] = __float2bfloat16_rn(g_G[i]);
}

// ---------------- U = A*G (2-term: (Ah+Al)*Gh), q folded ------------------------
__global__ void __launch_bounds__(256, 2) k_ug(const int* __restrict__ pairs,
                                               const float* __restrict__ emb) {
    extern __shared__ __align__(1024) char dsm[];
    const int tid = threadIdx.x, lane = tid & 31, w = tid >> 5;
    const int m0 = blockIdx.x * BM, n0 = blockIdx.y * BN;
    const uint32_t smb = cvta_smem(dsm);
    const int wm = (w >> 1) * 32, wn = (w & 1) * 64;
    const uint32_t aRow  = (uint32_t)(lane & 15);
    const uint32_t aColB = (uint32_t)((lane >> 4) * 16);
    const uint32_t grp   = (uint32_t)(lane >> 3);
    const uint32_t bRow  = (uint32_t)((lane & 7) + ((grp >> 1) * 8));
    const uint32_t bColB = (uint32_t)((grp & 1) * 16);

    float acc[2][8][4];
    #pragma unroll
    for (int mi = 0; mi < 2; mi++)
        #pragma unroll
        for (int ni = 0; ni < 8; ni++)
            #pragma unroll
            for (int q = 0; q < 4; q++) acc[mi][ni][q] = 0.f;

    auto load_chunk = [&](int c, int st) {
        uint32_t sb = smb + (uint32_t)st * UG_STAGE;
        #pragma unroll
        for (int i = 0; i < 4; i++) {
            int idx = tid + 256 * i, r = idx >> 3, seg = idx & 7;
            uint32_t so = swz((uint32_t)(r * 128 + seg * 16));
            cpasync16(sb + so,          g_Ab + (size_t)(m0 + r) * DIM + c * BK + seg * 8);
            cpasync16(sb + 16384u + so, g_Al + (size_t)(m0 + r) * DIM + c * BK + seg * 8);
            cpasync16(sb + 32768u + so, g_Gh + (size_t)(n0 + r) * DIM + c * BK + seg * 8);
        }
        COMMIT();
    };

    load_chunk(0, 0);
    __syncthreads();
    for (int c = 0; c < NCHUNK; c++) {
        if (c < NCHUNK - 1) { load_chunk(c + 1, (c + 1) & 1); WAIT1(); }
        else                  WAIT0();
        __syncthreads();
        uint32_t sb = smb + (uint32_t)(c & 1) * UG_STAGE;
        #pragma unroll
        for (int kk = 0; kk < 4; kk++) {
            uint32_t ah[2][4], al[2][4];
            #pragma unroll
            for (int mi = 0; mi < 2; mi++) {
                uint32_t so = swz((uint32_t)((wm + mi*16 + aRow)*128 + kk*32 + aColB));
                ldsm_x4(ah[mi], sb + so);
                ldsm_x4(al[mi], sb + 16384u + so);
            }
            uint32_t gh[4][4];
            #pragma unroll
            for (int nt = 0; nt < 4; nt++) {
                uint32_t so = swz((uint32_t)((wn + nt*16 + bRow)*128 + kk*32 + bColB));
                ldsm_x4(gh[nt], sb + 32768u + so);
            }
            #pragma unroll
            for (int mi = 0; mi < 2; mi++)
                #pragma unroll
                for (int nt = 0; nt < 4; nt++) {
                    mma16816(acc[mi][nt*2+0], ah[mi], &gh[nt][0]);
                    mma16816(acc[mi][nt*2+1], ah[mi], &gh[nt][2]);
                    mma16816(acc[mi][nt*2+0], al[mi], &gh[nt][0]);
                    mma16816(acc[mi][nt*2+1], al[mi], &gh[nt][2]);
                }
        }
        __syncthreads();
    }

    const int qr = lane >> 2, qc = lane & 3;
    #pragma unroll
    for (int mi = 0; mi < 2; mi++)
        #pragma unroll
        for (int h = 0; h < 2; h++) {
            int row = m0 + wm + mi * 16 + h * 8 + qr;
            int p = row & (BPAIRS - 1), side = row >> 11;
            int node = pairs[2 * p + side];
            const float* arow = emb + (size_t)node * DIM + n0;
            float qs = 0.f;
            #pragma unroll
            for (int ni = 0; ni < 8; ni++) {
                int col = wn + ni * 8 + qc * 2;
                qs += acc[mi][ni][h*2+0] * arow[col]
                    + acc[mi][ni][h*2+1] * arow[col + 1];
            }
            #pragma unroll
            for (int o = 1; o < 4; o <<= 1)
                qs += __shfl_xor_sync(0xffffffffu, qs, o);
            if (qc == 0) atomicAdd(&g_qrow[row], qs);
        }
}

// ---------------- per-row analytic stats ----------------------------------------
__global__ void __launch_bounds__(256) k_stats(const int* __restrict__ pairs,
                                               const float* __restrict__ emb) {
    int row = blockIdx.x * 8 + (threadIdx.x >> 5);
    if (row >= ROWS) return;
    int lane = threadIdx.x & 31;
    int p = row & (BPAIRS - 1), side = row >> 11;
    int li = pairs[2 * p], ri = pairs[2 * p + 1];
    int node = side ? ri : li;
    const float4* a4 = (const float4*)(emb + (size_t)node * DIM);
    const float4* S4 = (const float4*)g_S;
    const float4* T4 = (const float4*)g_T;
    float v = 0.f, wv = 0.f;
    #pragma unroll
    for (int i = lane; i < DIM / 4; i += 32) {
        float4 a = a4[i], s = S4[i], t = T4[i];
        v  += a.x*s.x + a.y*s.y + a.z*s.z + a.w*s.w;
        wv += a.x*t.x + a.y*t.y + a.z*t.z + a.w*t.w;
    }
    #pragma unroll
    for (int o = 16; o; o >>= 1) {
        v  += __shfl_xor_sync(0xffffffffu, v, o);
        wv += __shfl_xor_sync(0xffffffffu, wv, o);
    }
    if (lane == 0) {
        double N = (double)NODES;
        double pos = (double)g_pos[p], asq = (double)g_asq[row];
        double Q = g_Q, Q2 = g_Q2;
        double q = (double)g_qrow[row];
        double C = pos + GAMMA_ - asq;
        double SumX  = N * C - Q + 2.0 * (double)v;
        double mu    = (SumX - pos - 2.0 * GAMMA_) / N;
        double SumX2 = N*C*C - 2.0*C*Q + Q2 + 4.0*C*(double)v - 4.0*(double)wv
                       + 4.0*q;
        double E2 = SumX2;
        if (li != ri) {
            double xl = pos + GAMMA_;
            E2 -= xl * xl + GAMMA_ * GAMMA_;
        }
        double var = E2 / N - mu * mu;
        double sd  = sqrt(fmax(var, 1e-30));
        g_cb[row]   = (float)C;
        g_rsig[row] = (float)(LAMB_ / sd);
        g_zb[row]   = (float)(TAU_ - (double)KS_ - LAMB_ * mu / sd);
    }
}

// ---------------- main GEMM + gated exp (3-stage, fully unrolled chunks) ---------
__global__ void __launch_bounds__(256, 2) k_main(const int* __restrict__ pairs) {
    extern __shared__ __align__(1024) char dsm[];
    __shared__ float s_esq[BN], s_cb[BM], s_rsig[BM], s_zb[BM];
    __shared__ int   s_l[BM], s_r[BM];
    const int tid = threadIdx.x, lane = tid & 31, w = tid >> 5;
    const int m0 = blockIdx.x * BM, n0 = blockIdx.y * BN;
    const uint32_t smb = cvta_smem(dsm);

    if (tid < BM) {
        int row = m0 + tid;
        s_cb[tid] = g_cb[row]; s_rsig[tid] = g_rsig[row]; s_zb[tid] = g_zb[row];
        int p = row & (BPAIRS - 1);
        s_l[tid] = pairs[2 * p]; s_r[tid] = pairs[2 * p + 1];
        int col = n0 + tid;
        s_esq[tid] = (col < NODES) ? g_esq[col] : 0.f;
    }

    const int wm = (w >> 1) * 32, wn = (w & 1) * 64;
    const uint32_t aRow  = (uint32_t)(lane & 15);
    const uint32_t aColB = (uint32_t)((lane >> 4) * 16);
    const uint32_t grp   = (uint32_t)(lane >> 3);
    const uint32_t bRow  = (uint32_t)((lane & 7) + ((grp >> 1) * 8));
    const uint32_t bColB = (uint32_t)((grp & 1) * 16);

    float acc[2][8][4];
    #pragma unroll
    for (int mi = 0; mi < 2; mi++)
        #pragma unroll
        for (int ni = 0; ni < 8; ni++)
            #pragma unroll
            for (int q = 0; q < 4; q++) acc[mi][ni][q] = 0.f;

    auto load_chunk = [&](int c, int st) {
        uint32_t sb = smb + (uint32_t)st * STAGE_BYTES;
        #pragma unroll
        for (int i = 0; i < 4; i++) {
            int idx = tid + 256 * i, r = idx >> 3, seg = idx & 7;
            cpasync16(sb + swz((uint32_t)(r * 128 + seg * 16)),
                      g_Ab + (size_t)(m0 + r) * DIM + c * BK + seg * 8);
        }
        #pragma unroll
        for (int i = 0; i < 4; i++) {
            int idx = tid + 256 * i, r = idx >> 3, seg = idx & 7;
            cpasync16(sb + 16384u + swz((uint32_t)(r * 128 + seg * 16)),
                      g_Eb + (size_t)(n0 + r) * DIM + c * BK + seg * 8);
        }
        COMMIT();
    };

    load_chunk(0, 0);
    load_chunk(1, 1);
    // fully unrolled 3-stage pipeline: stage offsets constant-fold
    #pragma unroll
    for (int c = 0; c < NCHUNK; c++) {
        if (c < NCHUNK - 1) WAIT1(); else WAIT0();
        __syncthreads();
        if (c + 2 < NCHUNK) load_chunk(c + 2, (c + 2) % 3);
        uint32_t sA = smb + (uint32_t)((c % 3) * STAGE_BYTES), sB = sA + 16384u;
        #pragma unroll
        for (int kk = 0; kk < 4; kk++) {
            uint32_t a[2][4];
            #pragma unroll
            for (int mi = 0; mi < 2; mi++)
                ldsm_x4(a[mi], sA + swz((uint32_t)((wm + mi*16 + aRow)*128 + kk*32 + aColB)));
            uint32_t b[4][4];
            #pragma unroll
            for (int nt = 0; nt < 4; nt++)
                ldsm_x4(b[nt], sB + swz((uint32_t)((wn + nt*16 + bRow)*128 + kk*32 + bColB)));
            #pragma unroll
            for (int mi = 0; mi < 2; mi++)
                #pragma unroll
                for (int nt = 0; nt < 4; nt++) {
                    mma16816(acc[mi][nt*2+0], a[mi], &b[nt][0]);
                    mma16816(acc[mi][nt*2+1], a[mi], &b[nt][2]);
                }
        }
    }

    // ---- gated exp epilogue ----
    const int qr = lane >> 2, qc = lane & 3;
    #pragma unroll
    for (int mi = 0; mi < 2; mi++) {
        #pragma unroll
        for (int h = 0; h < 2; h++) {
            int rl  = wm + mi * 16 + h * 8 + qr;
            int row = m0 + rl;
            float cb = s_cb[rl], rsig = s_rsig[rl], zb = s_zb[rl];
            int li = s_l[rl], ri = s_r[rl];
            float psum = 0.f;
            #pragma unroll
            for (int ni = 0; ni < 8; ni++) {
                int tc0 = wn + ni * 8 + qc * 2;
                int col0 = n0 + tc0;
                float x0 = cb - s_esq[tc0]     + 2.f * acc[mi][ni][h*2+0];
                float x1 = cb - s_esq[tc0 + 1] + 2.f * acc[mi][ni][h*2+1];
                x0 *= 1.f - (float)(col0 == li)     - (float)(col0 == ri);
                x1 *= 1.f - (float)(col0 + 1 == li) - (float)(col0 + 1 == ri);
                float e0 = fmaf(rsig, x0, zb);
                float e1 = fmaf(rsig, x1, zb);
                if (col0 >= NODES) { e0 = -100.f; e1 = -100.f; }
                bool sig = fmaxf(e0, e1) > -25.f;
                if (__any_sync(0xffffffffu, sig))
                    psum += __expf(e0) + __expf(e1);
            }
            #pragma unroll
            for (int o = 1; o < 4; o <<= 1)
                psum += __shfl_xor_sync(0xffffffffu, psum, o);
            if (qc == 0 && psum != 0.f) atomicAdd(&g_sumexp[row], psum);
        }
    }
}

// ---------------- finalize --------------------------------------------------------
__global__ void k_final(float* __restrict__ out) {
    __shared__ float red[32];
    float t = 0.f;
    for (int row = threadIdx.x; row < ROWS; row += 1024)
        t += logf(g_sumexp[row]) + KS_;
    int lane = threadIdx.x & 31, wd = threadIdx.x >> 5;
    #pragma unroll
    for (int o = 16; o; o >>= 1) t += __shfl_xor_sync(0xffffffffu, t, o);
    if (lane == 0) red[wd] = t;
    __syncthreads();
    if (threadIdx.x < 32) {
        float v = red[threadIdx.x];
        #pragma unroll
        for (int o = 16; o; o >>= 1) v += __shfl_xor_sync(0xffffffffu, v, o);
        if (threadIdx.x == 0) out[0] = v * (1.f / BPAIRS);
    }
}

// ---------------- launch -----------------------------------------------------------
extern "C" void kernel_launch(void* const* d_in, const int* in_sizes, int n_in,
                              void* d_out, int out_size) {
    const int* pairs; const float* emb;
    if (in_sizes[0] == 2 * BPAIRS) { pairs = (const int*)d_in[0]; emb = (const float*)d_in[1]; }
    else                           { pairs = (const int*)d_in[1]; emb = (const float*)d_in[0]; }
    float* out = (float*)d_out;

    const int PREP_SMEM = 32 * PR_STRIDE * 4;
    cudaFuncSetAttribute(k_prep, cudaFuncAttributeMaxDynamicSharedMemorySize, PREP_SMEM);
    cudaFuncSetAttribute(k_gram, cudaFuncAttributeMaxDynamicSharedMemorySize, 2 * STAGE_BYTES);
    cudaFuncSetAttribute(k_ug,   cudaFuncAttributeMaxDynamicSharedMemorySize, 2 * UG_STAGE);
    cudaFuncSetAttribute(k_main, cudaFuncAttributeMaxDynamicSharedMemorySize, 3 * STAGE_BYTES);

    k_zero<<<(DIM * DIM + 255) / 256, 256>>>();
    k_prep<<<NODES / 32, 256, PREP_SMEM>>>(emb);
    k_gather<<<ROWS / 8, 256>>>(pairs, emb);
    k_pos<<<BPAIRS / 8, 256>>>(pairs, emb);

    dim3 gg(DIM / BM, DIM / BN, 23);
    k_gram<<<gg, 256, 2 * STAGE_BYTES>>>();
    k_gcvt<<<(DIM * DIM + 255) / 256, 256>>>();

    dim3 gu(ROWS / BM, DIM / BN);
    k_ug<<<gu, 256, 2 * UG_STAGE>>>(pairs, emb);
    k_stats<<<ROWS / 8, 256>>>(pairs, emb);

    dim3 gm(ROWS / BM, NPAD / BN);
    k_main<<<gm, 256, 3 * STAGE_BYTES>>>(pairs);

    k_final<<<1, 1024>>>(out);
}